// round 12
// baseline (speedup 1.0000x reference)
#include <cuda_runtime.h>

#define Bq 16
#define Sq 128
#define Dq 300
#define Oq 64
#define Eq 16
#define Tq 45
#define TP 48               // padded type count
#define ROWS_TOT 2048
#define WROW 316
#define KT 60               // K-chunk
#define CST 68              // smem col stride (floats): 272B, 16B-aligned
#define WBUF (64*CST)       // type-A per-buffer stride (64 cols)
#define CBUF (16*CST)       // type-B per-buffer stride (16 cols)

// __device__ scratch (allocation-free rule; zero-initialized)
__device__ float g_ht[ROWS_TOT*Oq];
__device__ float g_E [ROWS_TOT*TP];
__device__ float g_e [TP];          // zero-init covers t>=45
__device__ float g_C [Eq*304];      // C[e][k], rowlen 304

// ---------------------------------------------------------------------------
// cp.async helper
// ---------------------------------------------------------------------------
__device__ __forceinline__ void cp16(float* sdst, const float* gsrc) {
    unsigned a = (unsigned)__cvta_generic_to_shared(sdst);
    asm volatile("cp.async.cg.shared.global [%0], [%1], 16;" :: "r"(a), "l"(gsrc));
}

// ---------------------------------------------------------------------------
// P1: C[e][k] = sum_o W1[o][k]*W2[o][D+e] + W2[o][k]*W1[o][D+e]
//     19 blocks x 256 threads; block bx covers k = bx*16 .. bx*16+15.
//     Block 0 additionally computes Q/cb and e[t] = dt·cb + dtᵀQdt.
// ---------------------------------------------------------------------------
__global__ void __launch_bounds__(256) p1_kernel(
        const float* __restrict__ dep_table,
        const float* __restrict__ W1, const float* __restrict__ b1,
        const float* __restrict__ W2, const float* __restrict__ b2) {
    __shared__ float sWt1[Oq*Eq], sWt2[Oq*Eq];   // tails [o][e]
    __shared__ float sW1c[Oq*16], sW2c[Oq*16];   // k-panel [o][kk]
    __shared__ float sQ[256], scb[16];
    int tid = threadIdx.x;                       // 256 threads
    int kbase = blockIdx.x * 16;                 // 0..288 (g_C rowlen 304)

    // coalesced staging: thread -> (o = tid>>2, q = tid&3), one float4 each
    {
        int o = tid >> 2, q = tid & 3;
        *(float4*)&sWt1[o*Eq + q*4] = *(const float4*)&W1[o*WROW + Dq + q*4];
        *(float4*)&sWt2[o*Eq + q*4] = *(const float4*)&W2[o*WROW + Dq + q*4];
        *(float4*)&sW1c[o*16 + q*4] = *(const float4*)&W1[o*WROW + kbase + q*4];
        *(float4*)&sW2c[o*16 + q*4] = *(const float4*)&W2[o*WROW + kbase + q*4];
    }
    __syncthreads();

    // C: one output per thread; broadcast-friendly smem access
    {
        int e = tid & 15, kk = tid >> 4;
        float acc = 0.f;
        #pragma unroll 8
        for (int o = 0; o < Oq; o++)
            acc += sW1c[o*16 + kk] * sWt2[o*Eq + e]
                 + sW2c[o*16 + kk] * sWt1[o*Eq + e];
        g_C[e*304 + kbase + kk] = acc;           // k>=300 slots unused by gemm
    }

    if (blockIdx.x == 0) {
        // Q[e][ep] = sum_o Wt1[o][e]*Wt2[o][ep]; one entry per thread
        {
            int e = tid & 15, ep = tid >> 4;
            float q = 0.f;
            #pragma unroll 8
            for (int o = 0; o < Oq; o++)
                q += sWt1[o*Eq + e] * sWt2[o*Eq + ep];
            sQ[e*16 + ep] = q;
        }
        if (tid < 16) {
            float c = 0.f;
            #pragma unroll 8
            for (int o = 0; o < Oq; o++)
                c += b1[o] * sWt2[o*Eq + tid] + b2[o] * sWt1[o*Eq + tid];
            scb[tid] = c;
        }
        __syncthreads();
        if (tid < Tq) {
            float dte[Eq];
            #pragma unroll
            for (int e2 = 0; e2 < Eq; e2++) dte[e2] = dep_table[tid*Eq + e2];
            float acc = 0.f;
            #pragma unroll
            for (int e2 = 0; e2 < Eq; e2++) {
                float row = scb[e2];
                #pragma unroll
                for (int e3 = 0; e3 < Eq; e3++)
                    row += sQ[e2*16 + e3] * dte[e3];
                acc += dte[e2] * row;
            }
            g_e[tid] = acc;
        }
    }
}

// ---------------------------------------------------------------------------
// K1 (gemm): 192 blocks x 256 threads.
//   Type A (bx<128):  16 rows x 64 Wg cols -> g_ht
//   Type B (bx>=128): 32 rows x 16 C cols -> y; epilogue S = y·dt + e[t],
//                     row max, exp -> g_E.
// ---------------------------------------------------------------------------
__global__ void __launch_bounds__(256) gemm_kernel(
        const float* __restrict__ h,
        const float* __restrict__ Wg, const float* __restrict__ bg,
        const float* __restrict__ dep_table,
        const unsigned char* __restrict__ mask8) {
    extern __shared__ float sm[];
    __shared__ int sp[5];
    __shared__ float swt[32];
    __shared__ float smx[32];

    int tid  = threadIdx.x;
    int bx   = blockIdx.x;
    bool tb  = bx >= 128;
    int nrows = tb ? 32 : 16;
    int row0 = tb ? (bx - 128) * 32 : bx * 16;
    int b    = row0 >> 7;
    int ncols = tb ? Eq : Oq;

    float* sh2 = sm;
    float* sW  = sm + (tb ? 9600 : 4800);

    // ---- aspect span scan (dual bool-dtype robust) ----
    if (tid < 5) sp[tid] = (tid==0 || tid==3) ? Sq : ((tid==1 || tid==4) ? -1 : 0);
    __syncthreads();
    if (tid < 128 && mask8[(b<<7) + tid]) {
        atomicMin(&sp[0], tid); atomicMax(&sp[1], tid); atomicAdd(&sp[2], 1);
    }
    __syncthreads();
    bool valid8 = (sp[2] == 3 && sp[1] - sp[0] == 2);
    if (!valid8) {
        const int* m32 = (const int*)mask8;
        if (tid < 128 && m32[(b<<7) + tid] != 0) {
            atomicMin(&sp[3], tid); atomicMax(&sp[4], tid);
        }
    }
    __syncthreads();
    int st = valid8 ? sp[0] : sp[3];
    int en = valid8 ? sp[1] : sp[4];
    if (tid < nrows) {
        int s = (row0 + tid) & 127;
        float w;
        if (s < st)      w = 1.0f - (float)(st - s) * (1.0f/128.0f);
        else if (s > en) w = 1.0f - (float)(s - en) * (1.0f/128.0f);
        else             w = 0.0f;
        swt[tid] = w;
    }
    __syncthreads();

    // ---- stage position-weighted h, packed row pairs ----
    {
        const float4* h4 = (const float4*)(h + (size_t)row0 * Dq);
        for (int i = tid; i < nrows*75; i += 256) {
            int r = i / 75, q = i - r*75;
            float4 v = h4[i];
            float w = swt[r];
            float* dst = sh2 + ((r >> 1)*300 + q*4)*2 + (r & 1);
            dst[0] = v.x*w; dst[2] = v.y*w; dst[4] = v.z*w; dst[6] = v.w*w;
        }
    }

    int bufstride = tb ? CBUF : WBUF;
    #define STAGE_CHUNK(buf, cc)                                            \
        for (int i = tid; i < ncols*15; i += 256) {                         \
            int col = i / 15, q = i - col*15;                               \
            const float* src = tb                                           \
                ? g_C + (size_t)col * 304 + (cc)*KT + q*4                   \
                : Wg  + (size_t)col * Dq  + (cc)*KT + q*4;                  \
            cp16(&sW[(buf)*bufstride + col*CST + q*4], src);                \
        }                                                                   \
        asm volatile("cp.async.commit_group;" ::: "memory");

    STAGE_CHUNK(0, 0)
    const unsigned long long* sh2u = (const unsigned long long*)sh2;

    if (!tb) {
        // ---- type A: 16 rows x 64 cols; thread = (col, 2 pairs) ----
        int cg = tid & 63;
        int ph = tid >> 6;
        unsigned long long acc[2] = {0ull, 0ull};
        for (int c = 0; c < 5; c++) {
            if (c < 4) { STAGE_CHUNK((c+1)&1, c+1) }
            if (c < 4) asm volatile("cp.async.wait_group 1;" ::: "memory");
            else       asm volatile("cp.async.wait_group 0;" ::: "memory");
            __syncthreads();
            const float* wp = sW + (c & 1)*WBUF + cg*CST;
            #pragma unroll 5
            for (int k4 = 0; k4 < 15; k4++) {
                float4 wv = *(const float4*)&wp[k4*4];
                unsigned long long hk[2][4];
                #pragma unroll
                for (int j = 0; j < 2; j++) {
                    const unsigned long long* hp =
                        &sh2u[(size_t)(ph*2 + j)*300 + c*KT + k4*4];
                    ulonglong2 t0 = *(const ulonglong2*)(hp);
                    ulonglong2 t1 = *(const ulonglong2*)(hp + 2);
                    hk[j][0] = t0.x; hk[j][1] = t0.y; hk[j][2] = t1.x; hk[j][3] = t1.y;
                }
                #pragma unroll
                for (int kk = 0; kk < 4; kk++) {
                    unsigned long long wpk;
                    unsigned wu = __float_as_uint(((const float*)&wv)[kk]);
                    asm("mov.b64 %0, {%1, %1};" : "=l"(wpk) : "r"(wu));
                    #pragma unroll
                    for (int j = 0; j < 2; j++)
                        asm("fma.rn.f32x2 %0, %1, %2, %0;"
                            : "+l"(acc[j]) : "l"(hk[j][kk]), "l"(wpk));
                }
            }
            __syncthreads();
        }
        float bt = bg[cg];
        #pragma unroll
        for (int j = 0; j < 2; j++) {
            int r = (ph*2 + j)*2;
            unsigned lo = (unsigned)(acc[j] & 0xffffffffu);
            unsigned hi = (unsigned)(acc[j] >> 32);
            g_ht[(size_t)(row0 + r    )*Oq + cg] = __uint_as_float(lo) + bt;
            g_ht[(size_t)(row0 + r + 1)*Oq + cg] = __uint_as_float(hi) + bt;
        }
        return;
    }

    // ---- type B: 32 rows x 16 C cols; thread = (col e, pair p) ----
    {
        int e = tid & 15;
        int p = tid >> 4;          // 0..15 pairs -> rows 2p, 2p+1
        unsigned long long acc = 0ull;
        for (int c = 0; c < 5; c++) {
            if (c < 4) { STAGE_CHUNK((c+1)&1, c+1) }
            if (c < 4) asm volatile("cp.async.wait_group 1;" ::: "memory");
            else       asm volatile("cp.async.wait_group 0;" ::: "memory");
            __syncthreads();
            const float* wp = sW + (c & 1)*CBUF + e*CST;
            #pragma unroll 5
            for (int k4 = 0; k4 < 15; k4++) {
                float4 wv = *(const float4*)&wp[k4*4];
                const unsigned long long* hp =
                    &sh2u[(size_t)p*300 + c*KT + k4*4];
                ulonglong2 t0 = *(const ulonglong2*)(hp);
                ulonglong2 t1 = *(const ulonglong2*)(hp + 2);
                unsigned long long hk[4] = {t0.x, t0.y, t1.x, t1.y};
                #pragma unroll
                for (int kk = 0; kk < 4; kk++) {
                    unsigned long long wpk;
                    unsigned wu = __float_as_uint(((const float*)&wv)[kk]);
                    asm("mov.b64 %0, {%1, %1};" : "=l"(wpk) : "r"(wu));
                    asm("fma.rn.f32x2 %0, %1, %2, %0;"
                        : "+l"(acc) : "l"(hk[kk]), "l"(wpk));
                }
            }
            __syncthreads();
        }

        // epilogue smem (sh2/sW regions dead after last sync)
        float* sy  = sm;            // 32*16
        float* sdt = sm + 1024;     // 45*16
        float* se  = sm + 1792;     // 48
        float* ssv = sm + 2048;     // 32*48

        {
            unsigned lo = (unsigned)(acc & 0xffffffffu);
            unsigned hi = (unsigned)(acc >> 32);
            sy[(p*2    )*16 + e] = __uint_as_float(lo);
            sy[(p*2 + 1)*16 + e] = __uint_as_float(hi);
        }
        for (int i = tid; i < Tq*Eq; i += 256) sdt[i] = dep_table[i];
        if (tid < TP) se[tid] = g_e[tid];
        __syncthreads();

        // S[r][t] = y[r]·dt[t] + e[t]
        for (int i = tid; i < 32*TP; i += 256) {
            int r = i / TP, t = i - r*TP;
            float s;
            if (t < Tq) {
                s = se[t];
                const float* yr = sy + r*16;
                const float* dt = sdt + t*16;
                #pragma unroll
                for (int e2 = 0; e2 < Eq; e2++) s += yr[e2]*dt[e2];
            } else s = -1e30f;
            ssv[i] = s;
        }
        __syncthreads();
        if (tid < 32) {
            float m = -1e30f;
            #pragma unroll 8
            for (int t = 0; t < TP; t++) m = fmaxf(m, ssv[tid*TP + t]);
            smx[tid] = m;
        }
        __syncthreads();
        for (int i = tid; i < 32*TP; i += 256) {
            int r = i / TP, t = i - r*TP;
            float v = (t > 0 && t < Tq) ? __expf((ssv[i] - smx[r]) * 0.125f) : 0.f;
            g_E[(size_t)(row0 + r)*TP + t] = v;
        }
    }
    #undef STAGE_CHUNK
}

// ---------------------------------------------------------------------------
// K2 (attn): 512 blocks x 256 threads. Block = (8 rows, o-half of 32).
//   One warp per row: int4 dep gather (4 pos/lane) fused with row-sum.
// ---------------------------------------------------------------------------
__global__ void __launch_bounds__(256) attn_kernel(
        const int* __restrict__ dep,
        const float* __restrict__ bias,
        float* __restrict__ out) {
    __shared__ float sE[8*TP];
    __shared__ float sht[Sq*32];     // 16 KB
    __shared__ float sA[8*Sq];
    __shared__ float sden[8];

    int tid = threadIdx.x;
    int bx  = blockIdx.x;
    int rg  = bx >> 1, oh = bx & 1;
    int gr0 = rg * 8;
    int b   = gr0 >> 7;

    // prefetch h_trans half (128 rows x 32 floats)
    {
        const float* src = g_ht + ((size_t)b * Sq) * Oq + oh*32;
        for (int i = tid; i < Sq*8; i += 256) {
            int u = i >> 3, q = i & 7;
            cp16(&sht[u*32 + q*4], src + (size_t)u*Oq + q*4);
        }
        asm volatile("cp.async.commit_group;" ::: "memory");
    }
    for (int i = tid; i < 8*TP; i += 256) sE[i] = g_E[(size_t)gr0*TP + i];
    __syncthreads();

    int g = tid >> 5, lane = tid & 31;    // warp g = row g
    {
        int4 d = *(const int4*)&dep[(size_t)(gr0 + g)*Sq + lane*4];
        const float* Eg = sE + g*TP;
        float e0 = Eg[d.x], e1 = Eg[d.y], e2 = Eg[d.z], e3 = Eg[d.w];
        *(float4*)&sA[g*Sq + lane*4] = make_float4(e0, e1, e2, e3);
        float s = e0 + e1 + e2 + e3;
        #pragma unroll
        for (int off = 16; off; off >>= 1)
            s += __shfl_xor_sync(0xffffffffu, s, off);
        if (lane == 0) sden[g] = 1.0f / (s + 1e-6f);
    }
    asm volatile("cp.async.wait_group 0;" ::: "memory");
    __syncthreads();

    // matmul: one warp per row, lane = o within half
    const float* Ar = sA + g*Sq;
    float a = 0.f;
    #pragma unroll 8
    for (int u4 = 0; u4 < 32; u4++) {
        float4 av = *(const float4*)&Ar[u4*4];
        a += av.x * sht[(u4*4+0)*32 + lane]
           + av.y * sht[(u4*4+1)*32 + lane]
           + av.z * sht[(u4*4+2)*32 + lane]
           + av.w * sht[(u4*4+3)*32 + lane];
    }
    float v = a * sden[g] + bias[oh*32 + lane];
    out[(size_t)(gr0 + g)*Oq + oh*32 + lane] = fmaxf(v, 0.f);
}

// ---------------------------------------------------------------------------
// Inputs: h, dep_table, W1, b1, W2, b2, Wg, bg, bias, dep_type_matrix, aspect_mask
// ---------------------------------------------------------------------------
extern "C" void kernel_launch(void* const* d_in, const int* in_sizes, int n_in,
                              void* d_out, int out_size) {
    const float* h         = (const float*)d_in[0];
    const float* dep_table = (const float*)d_in[1];
    const float* W1        = (const float*)d_in[2];
    const float* b1        = (const float*)d_in[3];
    const float* W2        = (const float*)d_in[4];
    const float* b2        = (const float*)d_in[5];
    const float* Wg        = (const float*)d_in[6];
    const float* bg        = (const float*)d_in[7];
    const float* bias      = (const float*)d_in[8];
    const int*   dep       = (const int*)d_in[9];
    const unsigned char* mask = (const unsigned char*)d_in[10];

    const int gemm_smem = (4800 + 2*WBUF) * (int)sizeof(float);   // 54016 B
    cudaFuncSetAttribute(gemm_kernel,
                         cudaFuncAttributeMaxDynamicSharedMemorySize, gemm_smem);

    p1_kernel<<<19, 256>>>(dep_table, W1, b1, W2, b2);
    gemm_kernel<<<192, 256, gemm_smem>>>(h, Wg, bg, dep_table, mask);
    attn_kernel<<<512, 256>>>(dep, bias, (float*)d_out);
}

// round 13
// speedup vs baseline: 1.0873x; 1.0873x over previous
#include <cuda_runtime.h>

#define Bq 16
#define Sq 128
#define Dq 300
#define Oq 64
#define Eq 16
#define Tq 45
#define TP 48               // padded type count
#define ROWS_TOT 2048
#define WROW 316
#define KT 60               // K-chunk
#define CST 68              // smem col stride (floats): 272B, 16B-aligned
#define WBUF (64*CST)       // type-A per-buffer stride (64 cols)
#define CBUF (16*CST)       // type-B per-buffer stride (16 cols)
#define SMEM_FLOATS (4800 + 2*WBUF)   // 13504 floats = 54016 B

// __device__ scratch (allocation-free rule; zero-initialized)
__device__ float g_ht[ROWS_TOT*Oq];
__device__ float g_E [ROWS_TOT*TP];
__device__ float g_C [Eq*304];      // C[e][k], rowlen 304 (cols 300..303 unused)
__device__ int   g_flag;            // B-block C-slice completion counter

// ---------------------------------------------------------------------------
// cp.async helper
// ---------------------------------------------------------------------------
__device__ __forceinline__ void cp16(float* sdst, const float* gsrc) {
    unsigned a = (unsigned)__cvta_generic_to_shared(sdst);
    asm volatile("cp.async.cg.shared.global [%0], [%1], 16;" :: "r"(a), "l"(gsrc));
}

// ---------------------------------------------------------------------------
// K1 (fused gemm): 192 blocks x 256 threads.
//   Type A (bx<128):  16 rows x 64 Wg cols -> g_ht
//   Type B (bx>=128): prologue computes a C k-slice (producer) + Q/cb/e[t]
//     locally; spins on g_flag==64; then 32 rows x 16 C cols -> y;
//     epilogue S = y·dt + e[t], row max, exp -> g_E.
// ---------------------------------------------------------------------------
__global__ void __launch_bounds__(256) gemm_kernel(
        const float* __restrict__ h,
        const float* __restrict__ W1, const float* __restrict__ b1,
        const float* __restrict__ W2, const float* __restrict__ b2,
        const float* __restrict__ Wg, const float* __restrict__ bg,
        const float* __restrict__ dep_table,
        const unsigned char* __restrict__ mask8) {
    extern __shared__ float sm[];
    __shared__ int sp[5];
    __shared__ float swt[32];
    __shared__ float smx[32];

    int tid  = threadIdx.x;
    int bx   = blockIdx.x;
    bool tb  = bx >= 128;
    int nrows = tb ? 32 : 16;
    int row0 = tb ? (bx - 128) * 32 : bx * 16;
    int b    = row0 >> 7;
    int ncols = tb ? Eq : Oq;

    float* sh2 = sm;
    float* sW  = sm + (tb ? 9600 : 4800);
    float* se  = sm + SMEM_FLOATS - 64;   // persistent e[t] (B only)

    // ================= type-B prologue: produce C slice + Q/cb/e =========
    if (tb) {
        float* sWt1 = sm;            // tails [o][e] 1024
        float* sWt2 = sm + 1024;
        float* sW1c = sm + 2048;     // k-panel [o][j] 64*8
        float* sW2c = sm + 2560;
        float* sb1  = sm + 3072;     // 64
        float* sb2  = sm + 3136;
        float* sQ   = sm + 3200;     // 256
        float* scb  = sm + 3456;     // 16

        int bb = bx - 128;           // 0..63; slices 0..59 cover k=0..299
        int k0 = bb * 5;
        {
            int o = tid >> 2, q = tid & 3;
            *(float4*)&sWt1[o*Eq + q*4] = *(const float4*)&W1[o*WROW + Dq + q*4];
            *(float4*)&sWt2[o*Eq + q*4] = *(const float4*)&W2[o*WROW + Dq + q*4];
        }
        if (tid < 64) { sb1[tid] = b1[tid]; sb2[tid] = b2[tid]; }
        if (bb < 60 && tid < 64) {
            #pragma unroll
            for (int j = 0; j < 5; j++) {
                sW1c[tid*8 + j] = W1[tid*WROW + k0 + j];
                sW2c[tid*8 + j] = W2[tid*WROW + k0 + j];
            }
        }
        __syncthreads();

        // C slice: threads 0..79 -> (e = tid&15, j = tid>>4)
        if (bb < 60 && tid < 80) {
            int e = tid & 15, j = tid >> 4;
            float acc = 0.f;
            #pragma unroll 8
            for (int o = 0; o < Oq; o++)
                acc += sW1c[o*8 + j] * sWt2[o*Eq + e]
                     + sW2c[o*8 + j] * sWt1[o*Eq + e];
            g_C[e*304 + k0 + j] = acc;
        }
        // Q[e][ep]: one entry per thread
        {
            int e = tid & 15, ep = tid >> 4;
            float q = 0.f;
            #pragma unroll 8
            for (int o = 0; o < Oq; o++)
                q += sWt1[o*Eq + e] * sWt2[o*Eq + ep];
            sQ[e*16 + ep] = q;
        }
        if (tid < 16) {
            float c = 0.f;
            #pragma unroll 8
            for (int o = 0; o < Oq; o++)
                c += sb1[o] * sWt2[o*Eq + tid] + sb2[o] * sWt1[o*Eq + tid];
            scb[tid] = c;
        }
        __threadfence();             // make this block's g_C stores visible
        __syncthreads();
        if (tid == 0) atomicAdd(&g_flag, 1);

        // e[t] = dt·cb + dtᵀ Q dt  (local, overlaps other blocks' C work)
        if (tid < TP) {
            float ev = 0.f;
            if (tid < Tq) {
                float dte[Eq];
                #pragma unroll
                for (int e2 = 0; e2 < Eq; e2++) dte[e2] = dep_table[tid*Eq + e2];
                #pragma unroll
                for (int e2 = 0; e2 < Eq; e2++) {
                    float row = scb[e2];
                    #pragma unroll
                    for (int e3 = 0; e3 < Eq; e3++)
                        row += sQ[e2*16 + e3] * dte[e3];
                    ev += dte[e2] * row;
                }
            }
            se[tid] = ev;
        }
        __syncthreads();             // prologue smem dead below (except se)
    }

    // ================= span scan (dual bool-dtype robust) ================
    if (tid < 5) sp[tid] = (tid==0 || tid==3) ? Sq : ((tid==1 || tid==4) ? -1 : 0);
    __syncthreads();
    if (tid < 128 && mask8[(b<<7) + tid]) {
        atomicMin(&sp[0], tid); atomicMax(&sp[1], tid); atomicAdd(&sp[2], 1);
    }
    __syncthreads();
    bool valid8 = (sp[2] == 3 && sp[1] - sp[0] == 2);
    if (!valid8) {
        const int* m32 = (const int*)mask8;
        if (tid < 128 && m32[(b<<7) + tid] != 0) {
            atomicMin(&sp[3], tid); atomicMax(&sp[4], tid);
        }
    }
    __syncthreads();
    int st = valid8 ? sp[0] : sp[3];
    int en = valid8 ? sp[1] : sp[4];
    if (tid < nrows) {
        int s = (row0 + tid) & 127;
        float w;
        if (s < st)      w = 1.0f - (float)(st - s) * (1.0f/128.0f);
        else if (s > en) w = 1.0f - (float)(s - en) * (1.0f/128.0f);
        else             w = 0.0f;
        swt[tid] = w;
    }
    __syncthreads();

    // ---- stage position-weighted h, packed row pairs ----
    {
        const float4* h4 = (const float4*)(h + (size_t)row0 * Dq);
        for (int i = tid; i < nrows*75; i += 256) {
            int r = i / 75, q = i - r*75;
            float4 v = h4[i];
            float w = swt[r];
            float* dst = sh2 + ((r >> 1)*300 + q*4)*2 + (r & 1);
            dst[0] = v.x*w; dst[2] = v.y*w; dst[4] = v.z*w; dst[6] = v.w*w;
        }
    }

    // B blocks: wait for all C slices before reading g_C
    if (tb) {
        __syncthreads();
        if (tid == 0) {
            while (atomicAdd(&g_flag, 0) < 64) __nanosleep(64);
            __threadfence();
        }
        __syncthreads();
    }

    int bufstride = tb ? CBUF : WBUF;
    #define STAGE_CHUNK(buf, cc)                                            \
        for (int i = tid; i < ncols*15; i += 256) {                         \
            int col = i / 15, q = i - col*15;                               \
            const float* src = tb                                           \
                ? g_C + (size_t)col * 304 + (cc)*KT + q*4                   \
                : Wg  + (size_t)col * Dq  + (cc)*KT + q*4;                  \
            cp16(&sW[(buf)*bufstride + col*CST + q*4], src);                \
        }                                                                   \
        asm volatile("cp.async.commit_group;" ::: "memory");

    STAGE_CHUNK(0, 0)
    const unsigned long long* sh2u = (const unsigned long long*)sh2;

    if (!tb) {
        // ---- type A: 16 rows x 64 cols; thread = (col, 2 pairs) ----
        int cg = tid & 63;
        int ph = tid >> 6;
        unsigned long long acc[2] = {0ull, 0ull};
        for (int c = 0; c < 5; c++) {
            if (c < 4) { STAGE_CHUNK((c+1)&1, c+1) }
            if (c < 4) asm volatile("cp.async.wait_group 1;" ::: "memory");
            else       asm volatile("cp.async.wait_group 0;" ::: "memory");
            __syncthreads();
            const float* wp = sW + (c & 1)*WBUF + cg*CST;
            #pragma unroll 5
            for (int k4 = 0; k4 < 15; k4++) {
                float4 wv = *(const float4*)&wp[k4*4];
                unsigned long long hk[2][4];
                #pragma unroll
                for (int j = 0; j < 2; j++) {
                    const unsigned long long* hp =
                        &sh2u[(size_t)(ph*2 + j)*300 + c*KT + k4*4];
                    ulonglong2 t0 = *(const ulonglong2*)(hp);
                    ulonglong2 t1 = *(const ulonglong2*)(hp + 2);
                    hk[j][0] = t0.x; hk[j][1] = t0.y; hk[j][2] = t1.x; hk[j][3] = t1.y;
                }
                #pragma unroll
                for (int kk = 0; kk < 4; kk++) {
                    unsigned long long wpk;
                    unsigned wu = __float_as_uint(((const float*)&wv)[kk]);
                    asm("mov.b64 %0, {%1, %1};" : "=l"(wpk) : "r"(wu));
                    #pragma unroll
                    for (int j = 0; j < 2; j++)
                        asm("fma.rn.f32x2 %0, %1, %2, %0;"
                            : "+l"(acc[j]) : "l"(hk[j][kk]), "l"(wpk));
                }
            }
            __syncthreads();
        }
        float bt = bg[cg];
        #pragma unroll
        for (int j = 0; j < 2; j++) {
            int r = (ph*2 + j)*2;
            unsigned lo = (unsigned)(acc[j] & 0xffffffffu);
            unsigned hi = (unsigned)(acc[j] >> 32);
            g_ht[(size_t)(row0 + r    )*Oq + cg] = __uint_as_float(lo) + bt;
            g_ht[(size_t)(row0 + r + 1)*Oq + cg] = __uint_as_float(hi) + bt;
        }
        return;
    }

    // ---- type B: 32 rows x 16 C cols; thread = (col e, pair p) ----
    {
        int e = tid & 15;
        int p = tid >> 4;          // 0..15 pairs -> rows 2p, 2p+1
        unsigned long long acc = 0ull;
        for (int c = 0; c < 5; c++) {
            if (c < 4) { STAGE_CHUNK((c+1)&1, c+1) }
            if (c < 4) asm volatile("cp.async.wait_group 1;" ::: "memory");
            else       asm volatile("cp.async.wait_group 0;" ::: "memory");
            __syncthreads();
            const float* wp = sW + (c & 1)*CBUF + e*CST;
            #pragma unroll 5
            for (int k4 = 0; k4 < 15; k4++) {
                float4 wv = *(const float4*)&wp[k4*4];
                const unsigned long long* hp =
                    &sh2u[(size_t)p*300 + c*KT + k4*4];
                ulonglong2 t0 = *(const ulonglong2*)(hp);
                ulonglong2 t1 = *(const ulonglong2*)(hp + 2);
                unsigned long long hk[4] = {t0.x, t0.y, t1.x, t1.y};
                #pragma unroll
                for (int kk = 0; kk < 4; kk++) {
                    unsigned long long wpk;
                    unsigned wu = __float_as_uint(((const float*)&wv)[kk]);
                    asm("mov.b64 %0, {%1, %1};" : "=l"(wpk) : "r"(wu));
                    asm("fma.rn.f32x2 %0, %1, %2, %0;"
                        : "+l"(acc) : "l"(hk[kk]), "l"(wpk));
                }
            }
            __syncthreads();
        }

        // epilogue smem (sh2/sW regions dead; se persists at tail)
        float* sy  = sm;            // 32*16
        float* sdt = sm + 1024;     // 45*16
        float* ssv = sm + 2048;     // 32*48

        {
            unsigned lo = (unsigned)(acc & 0xffffffffu);
            unsigned hi = (unsigned)(acc >> 32);
            sy[(p*2    )*16 + e] = __uint_as_float(lo);
            sy[(p*2 + 1)*16 + e] = __uint_as_float(hi);
        }
        for (int i = tid; i < Tq*Eq; i += 256) sdt[i] = dep_table[i];
        __syncthreads();

        // S[r][t] = y[r]·dt[t] + e[t]
        for (int i = tid; i < 32*TP; i += 256) {
            int r = i / TP, t = i - r*TP;
            float s;
            if (t < Tq) {
                s = se[t];
                const float* yr = sy + r*16;
                const float* dt = sdt + t*16;
                #pragma unroll
                for (int e2 = 0; e2 < Eq; e2++) s += yr[e2]*dt[e2];
            } else s = -1e30f;
            ssv[i] = s;
        }
        __syncthreads();
        if (tid < 32) {
            float m = -1e30f;
            #pragma unroll 8
            for (int t = 0; t < TP; t++) m = fmaxf(m, ssv[tid*TP + t]);
            smx[tid] = m;
        }
        __syncthreads();
        for (int i = tid; i < 32*TP; i += 256) {
            int r = i / TP, t = i - r*TP;
            float v = (t > 0 && t < Tq) ? __expf((ssv[i] - smx[r]) * 0.125f) : 0.f;
            g_E[(size_t)(row0 + r)*TP + t] = v;
        }
    }
    #undef STAGE_CHUNK
}

// ---------------------------------------------------------------------------
// K2 (attn): 512 blocks x 256 threads. Block = (8 rows, o-half of 32).
//   Block 0 resets g_flag for the next graph replay.
// ---------------------------------------------------------------------------
__global__ void __launch_bounds__(256) attn_kernel(
        const int* __restrict__ dep,
        const float* __restrict__ bias,
        float* __restrict__ out) {
    __shared__ float sE[8*TP];
    __shared__ float sht[Sq*32];     // 16 KB
    __shared__ float sA[8*Sq];
    __shared__ float sden[8];

    int tid = threadIdx.x;
    int bx  = blockIdx.x;
    if (bx == 0 && tid == 0) g_flag = 0;   // reset for next replay
    int rg  = bx >> 1, oh = bx & 1;
    int gr0 = rg * 8;
    int b   = gr0 >> 7;

    // prefetch h_trans half (128 rows x 32 floats)
    {
        const float* src = g_ht + ((size_t)b * Sq) * Oq + oh*32;
        for (int i = tid; i < Sq*8; i += 256) {
            int u = i >> 3, q = i & 7;
            cp16(&sht[u*32 + q*4], src + (size_t)u*Oq + q*4);
        }
        asm volatile("cp.async.commit_group;" ::: "memory");
    }
    for (int i = tid; i < 8*TP; i += 256) sE[i] = g_E[(size_t)gr0*TP + i];
    __syncthreads();

    int g = tid >> 5, lane = tid & 31;    // warp g = row g
    {
        int4 d = *(const int4*)&dep[(size_t)(gr0 + g)*Sq + lane*4];
        const float* Eg = sE + g*TP;
        float e0 = Eg[d.x], e1 = Eg[d.y], e2 = Eg[d.z], e3 = Eg[d.w];
        *(float4*)&sA[g*Sq + lane*4] = make_float4(e0, e1, e2, e3);
        float s = e0 + e1 + e2 + e3;
        #pragma unroll
        for (int off = 16; off; off >>= 1)
            s += __shfl_xor_sync(0xffffffffu, s, off);
        if (lane == 0) sden[g] = 1.0f / (s + 1e-6f);
    }
    asm volatile("cp.async.wait_group 0;" ::: "memory");
    __syncthreads();

    // matmul: one warp per row, lane = o within half
    const float* Ar = sA + g*Sq;
    float a = 0.f;
    #pragma unroll 8
    for (int u4 = 0; u4 < 32; u4++) {
        float4 av = *(const float4*)&Ar[u4*4];
        a += av.x * sht[(u4*4+0)*32 + lane]
           + av.y * sht[(u4*4+1)*32 + lane]
           + av.z * sht[(u4*4+2)*32 + lane]
           + av.w * sht[(u4*4+3)*32 + lane];
    }
    float v = a * sden[g] + bias[oh*32 + lane];
    out[(size_t)(gr0 + g)*Oq + oh*32 + lane] = fmaxf(v, 0.f);
}

// ---------------------------------------------------------------------------
// Inputs: h, dep_table, W1, b1, W2, b2, Wg, bg, bias, dep_type_matrix, aspect_mask
// ---------------------------------------------------------------------------
extern "C" void kernel_launch(void* const* d_in, const int* in_sizes, int n_in,
                              void* d_out, int out_size) {
    const float* h         = (const float*)d_in[0];
    const float* dep_table = (const float*)d_in[1];
    const float* W1        = (const float*)d_in[2];
    const float* b1        = (const float*)d_in[3];
    const float* W2        = (const float*)d_in[4];
    const float* b2        = (const float*)d_in[5];
    const float* Wg        = (const float*)d_in[6];
    const float* bg        = (const float*)d_in[7];
    const float* bias      = (const float*)d_in[8];
    const int*   dep       = (const int*)d_in[9];
    const unsigned char* mask = (const unsigned char*)d_in[10];

    const int gemm_smem = SMEM_FLOATS * (int)sizeof(float);   // 54016 B
    cudaFuncSetAttribute(gemm_kernel,
                         cudaFuncAttributeMaxDynamicSharedMemorySize, gemm_smem);

    gemm_kernel<<<192, 256, gemm_smem>>>(h, W1, b1, W2, b2, Wg, bg,
                                         dep_table, mask);
    attn_kernel<<<512, 256>>>(dep, bias, (float*)d_out);
}

// round 14
// speedup vs baseline: 1.1469x; 1.0548x over previous
#include <cuda_runtime.h>

#define Bq 16
#define Sq 128
#define Dq 300
#define Oq 64
#define Eq 16
#define Tq 45
#define TP 48               // padded type count
#define ROWS_TOT 2048
#define WROW 316
#define KT 60               // K-chunk
#define CST 68              // smem col stride (floats): 272B, 16B-aligned
#define WBUF (64*CST)       // type-A per-buffer stride (64 cols)
#define CBUF (16*CST)       // type-B per-buffer stride (16 cols)
#define SMEM_FLOATS (4800 + 2*WBUF)   // 13504 floats = 54016 B

// __device__ scratch (allocation-free rule; zero-initialized)
__device__ float g_ht[ROWS_TOT*Oq];
__device__ float g_E [ROWS_TOT*TP];
__device__ float g_C [Eq*304];      // C[e][k], rowlen 304 (cols 300..303 unused)
__device__ int   g_syncC;           // B-block C-slice completion counter (target 64)
__device__ int   g_cntA[Bq];        // per-batch A-block done counters (target 8)
__device__ int   g_cntB[Bq];        // per-batch B-block done counters (target 4)
__device__ int   g_done;            // attn completion counter (target 512)

// ---------------------------------------------------------------------------
// cp.async helper
// ---------------------------------------------------------------------------
__device__ __forceinline__ void cp16(float* sdst, const float* gsrc) {
    unsigned a = (unsigned)__cvta_generic_to_shared(sdst);
    asm volatile("cp.async.cg.shared.global [%0], [%1], 16;" :: "r"(a), "l"(gsrc));
}

// ---------------------------------------------------------------------------
// Fused kernel: 704 blocks x 256 threads, 54 KB dynamic smem.
//   bx <  128 : type A gemm — 16 rows x 64 Wg cols -> g_ht; bump cntA[b].
//   128..191  : type B gemm — C-slice producer + 32 rows x 16 C cols -> y;
//               softmax table -> g_E; bump cntB[b].
//   bx >= 192 : attn — prefetch dep/bias, spin on cntA/cntB[b], then
//               gather+row-sum+matmul -> out. Last attn block resets flags.
// Deadlock-safety: 4 blocks/SM (54KB) => 592 wave-1 slots >= 192 producers.
// ---------------------------------------------------------------------------
__global__ void __launch_bounds__(256) fused_kernel(
        const float* __restrict__ h,
        const float* __restrict__ W1, const float* __restrict__ b1,
        const float* __restrict__ W2, const float* __restrict__ b2,
        const float* __restrict__ Wg, const float* __restrict__ bg,
        const float* __restrict__ dep_table,
        const unsigned char* __restrict__ mask8,
        const int* __restrict__ dep,
        const float* __restrict__ bias,
        float* __restrict__ out) {
    extern __shared__ float sm[];
    __shared__ int sp[5];
    __shared__ float swt[32];
    __shared__ float smx[32];

    int tid  = threadIdx.x;
    int bx   = blockIdx.x;

    // ===================== ATTN ROLE (bx >= 192) =========================
    if (bx >= 192) {
        float* sE   = sm;            // 384
        float* sht  = sm + 384;      // 4096
        float* sA   = sm + 4480;     // 1024
        float* sden = sm + 5504;     // 8

        int abx = bx - 192;          // 0..511
        int rg2 = abx >> 1, oh = abx & 1;
        int gr0 = rg2 * 8;
        int b   = gr0 >> 7;
        int g = tid >> 5, lane = tid & 31;

        // prefetch (independent of producers)
        int4 d = *(const int4*)&dep[(size_t)(gr0 + g)*Sq + lane*4];
        float bo = bias[oh*32 + lane];

        // wait for this batch's g_ht (8 A-blocks) and g_E (4 B-blocks)
        if (tid == 0) {
            while (atomicAdd(&g_cntA[b], 0) < 8 ||
                   atomicAdd(&g_cntB[b], 0) < 4)
                __nanosleep(128);
            __threadfence();
        }
        __syncthreads();

        // stage h_trans half (128 rows x 32 floats) via cp.async
        {
            const float* src = g_ht + ((size_t)b * Sq) * Oq + oh*32;
            for (int i = tid; i < Sq*8; i += 256) {
                int u = i >> 3, q = i & 7;
                cp16(&sht[u*32 + q*4], src + (size_t)u*Oq + q*4);
            }
            asm volatile("cp.async.commit_group;" ::: "memory");
        }
        for (int i = tid; i < 8*TP; i += 256) sE[i] = g_E[(size_t)gr0*TP + i];
        __syncthreads();

        // gather e = E[ty] fused with row-sum (one warp per row)
        {
            const float* Eg = sE + g*TP;
            float e0 = Eg[d.x], e1 = Eg[d.y], e2 = Eg[d.z], e3 = Eg[d.w];
            *(float4*)&sA[g*Sq + lane*4] = make_float4(e0, e1, e2, e3);
            float s = e0 + e1 + e2 + e3;
            #pragma unroll
            for (int off = 16; off; off >>= 1)
                s += __shfl_xor_sync(0xffffffffu, s, off);
            if (lane == 0) sden[g] = 1.0f / (s + 1e-6f);
        }
        asm volatile("cp.async.wait_group 0;" ::: "memory");
        __syncthreads();

        // matmul: one warp per row, lane = o within half
        const float* Ar = sA + g*Sq;
        float a = 0.f;
        #pragma unroll 8
        for (int u4 = 0; u4 < 32; u4++) {
            float4 av = *(const float4*)&Ar[u4*4];
            a += av.x * sht[(u4*4+0)*32 + lane]
               + av.y * sht[(u4*4+1)*32 + lane]
               + av.z * sht[(u4*4+2)*32 + lane]
               + av.w * sht[(u4*4+3)*32 + lane];
        }
        float v = a * sden[g] + bo;
        out[(size_t)(gr0 + g)*Oq + oh*32 + lane] = fmaxf(v, 0.f);

        // completion count; 512th block resets all flags for next replay
        if (tid == 0) {
            int vdone = atomicAdd(&g_done, 1);
            if (vdone == 511) {
                g_done = 0;
                g_syncC = 0;
                #pragma unroll
                for (int i = 0; i < Bq; i++) { g_cntA[i] = 0; g_cntB[i] = 0; }
            }
        }
        return;
    }

    // ===================== GEMM ROLES (bx < 192) =========================
    bool tb  = bx >= 128;
    int nrows = tb ? 32 : 16;
    int row0 = tb ? (bx - 128) * 32 : bx * 16;
    int b    = row0 >> 7;
    int ncols = tb ? Eq : Oq;

    float* sh2 = sm;
    float* sW  = sm + (tb ? 9600 : 4800);
    float* se  = sm + SMEM_FLOATS - 64;   // persistent e[t] (B only)

    // ---- type-B prologue: produce C slice + Q/cb/e ----
    if (tb) {
        float* sWt1 = sm;            // tails [o][e] 1024
        float* sWt2 = sm + 1024;
        float* sW1c = sm + 2048;     // k-panel [o][j] 64*8
        float* sW2c = sm + 2560;
        float* sb1  = sm + 3072;     // 64
        float* sb2  = sm + 3136;
        float* sQ   = sm + 3200;     // 256
        float* scb  = sm + 3456;     // 16

        int bb = bx - 128;           // 0..63; slices 0..59 cover k=0..299
        int k0 = bb * 5;
        {
            int o = tid >> 2, q = tid & 3;
            *(float4*)&sWt1[o*Eq + q*4] = *(const float4*)&W1[o*WROW + Dq + q*4];
            *(float4*)&sWt2[o*Eq + q*4] = *(const float4*)&W2[o*WROW + Dq + q*4];
        }
        if (tid < 64) { sb1[tid] = b1[tid]; sb2[tid] = b2[tid]; }
        if (bb < 60 && tid < 64) {
            #pragma unroll
            for (int j = 0; j < 5; j++) {
                sW1c[tid*8 + j] = W1[tid*WROW + k0 + j];
                sW2c[tid*8 + j] = W2[tid*WROW + k0 + j];
            }
        }
        __syncthreads();

        if (bb < 60 && tid < 80) {
            int e = tid & 15, j = tid >> 4;
            float acc = 0.f;
            #pragma unroll 8
            for (int o = 0; o < Oq; o++)
                acc += sW1c[o*8 + j] * sWt2[o*Eq + e]
                     + sW2c[o*8 + j] * sWt1[o*Eq + e];
            g_C[e*304 + k0 + j] = acc;
        }
        {
            int e = tid & 15, ep = tid >> 4;
            float q = 0.f;
            #pragma unroll 8
            for (int o = 0; o < Oq; o++)
                q += sWt1[o*Eq + e] * sWt2[o*Eq + ep];
            sQ[e*16 + ep] = q;
        }
        if (tid < 16) {
            float c = 0.f;
            #pragma unroll 8
            for (int o = 0; o < Oq; o++)
                c += sb1[o] * sWt2[o*Eq + tid] + sb2[o] * sWt1[o*Eq + tid];
            scb[tid] = c;
        }
        __threadfence();
        __syncthreads();
        if (tid == 0) atomicAdd(&g_syncC, 1);

        if (tid < TP) {
            float ev = 0.f;
            if (tid < Tq) {
                float dte[Eq];
                #pragma unroll
                for (int e2 = 0; e2 < Eq; e2++) dte[e2] = dep_table[tid*Eq + e2];
                #pragma unroll
                for (int e2 = 0; e2 < Eq; e2++) {
                    float row = scb[e2];
                    #pragma unroll
                    for (int e3 = 0; e3 < Eq; e3++)
                        row += sQ[e2*16 + e3] * dte[e3];
                    ev += dte[e2] * row;
                }
            }
            se[tid] = ev;
        }
        __syncthreads();
    }

    // ---- span scan (dual bool-dtype robust) ----
    if (tid < 5) sp[tid] = (tid==0 || tid==3) ? Sq : ((tid==1 || tid==4) ? -1 : 0);
    __syncthreads();
    if (tid < 128 && mask8[(b<<7) + tid]) {
        atomicMin(&sp[0], tid); atomicMax(&sp[1], tid); atomicAdd(&sp[2], 1);
    }
    __syncthreads();
    bool valid8 = (sp[2] == 3 && sp[1] - sp[0] == 2);
    if (!valid8) {
        const int* m32 = (const int*)mask8;
        if (tid < 128 && m32[(b<<7) + tid] != 0) {
            atomicMin(&sp[3], tid); atomicMax(&sp[4], tid);
        }
    }
    __syncthreads();
    int st = valid8 ? sp[0] : sp[3];
    int en = valid8 ? sp[1] : sp[4];
    if (tid < nrows) {
        int s = (row0 + tid) & 127;
        float w;
        if (s < st)      w = 1.0f - (float)(st - s) * (1.0f/128.0f);
        else if (s > en) w = 1.0f - (float)(s - en) * (1.0f/128.0f);
        else             w = 0.0f;
        swt[tid] = w;
    }
    __syncthreads();

    // ---- stage position-weighted h, packed row pairs ----
    {
        const float4* h4 = (const float4*)(h + (size_t)row0 * Dq);
        for (int i = tid; i < nrows*75; i += 256) {
            int r = i / 75, q = i - r*75;
            float4 v = h4[i];
            float w = swt[r];
            float* dst = sh2 + ((r >> 1)*300 + q*4)*2 + (r & 1);
            dst[0] = v.x*w; dst[2] = v.y*w; dst[4] = v.z*w; dst[6] = v.w*w;
        }
    }

    // B blocks: wait for all C slices before reading g_C
    if (tb) {
        __syncthreads();
        if (tid == 0) {
            while (atomicAdd(&g_syncC, 0) < 64) __nanosleep(64);
            __threadfence();
        }
        __syncthreads();
    }

    int bufstride = tb ? CBUF : WBUF;
    #define STAGE_CHUNK(buf, cc)                                            \
        for (int i = tid; i < ncols*15; i += 256) {                         \
            int col = i / 15, q = i - col*15;                               \
            const float* src = tb                                           \
                ? g_C + (size_t)col * 304 + (cc)*KT + q*4                   \
                : Wg  + (size_t)col * Dq  + (cc)*KT + q*4;                  \
            cp16(&sW[(buf)*bufstride + col*CST + q*4], src);                \
        }                                                                   \
        asm volatile("cp.async.commit_group;" ::: "memory");

    STAGE_CHUNK(0, 0)
    const unsigned long long* sh2u = (const unsigned long long*)sh2;

    if (!tb) {
        // ---- type A: 16 rows x 64 cols; thread = (col, 2 pairs) ----
        int cg = tid & 63;
        int ph = tid >> 6;
        unsigned long long acc[2] = {0ull, 0ull};
        for (int c = 0; c < 5; c++) {
            if (c < 4) { STAGE_CHUNK((c+1)&1, c+1) }
            if (c < 4) asm volatile("cp.async.wait_group 1;" ::: "memory");
            else       asm volatile("cp.async.wait_group 0;" ::: "memory");
            __syncthreads();
            const float* wp = sW + (c & 1)*WBUF + cg*CST;
            #pragma unroll 5
            for (int k4 = 0; k4 < 15; k4++) {
                float4 wv = *(const float4*)&wp[k4*4];
                unsigned long long hk[2][4];
                #pragma unroll
                for (int j = 0; j < 2; j++) {
                    const unsigned long long* hp =
                        &sh2u[(size_t)(ph*2 + j)*300 + c*KT + k4*4];
                    ulonglong2 t0 = *(const ulonglong2*)(hp);
                    ulonglong2 t1 = *(const ulonglong2*)(hp + 2);
                    hk[j][0] = t0.x; hk[j][1] = t0.y; hk[j][2] = t1.x; hk[j][3] = t1.y;
                }
                #pragma unroll
                for (int kk = 0; kk < 4; kk++) {
                    unsigned long long wpk;
                    unsigned wu = __float_as_uint(((const float*)&wv)[kk]);
                    asm("mov.b64 %0, {%1, %1};" : "=l"(wpk) : "r"(wu));
                    #pragma unroll
                    for (int j = 0; j < 2; j++)
                        asm("fma.rn.f32x2 %0, %1, %2, %0;"
                            : "+l"(acc[j]) : "l"(hk[j][kk]), "l"(wpk));
                }
            }
            __syncthreads();
        }
        float bt = bg[cg];
        #pragma unroll
        for (int j = 0; j < 2; j++) {
            int r = (ph*2 + j)*2;
            unsigned lo = (unsigned)(acc[j] & 0xffffffffu);
            unsigned hi = (unsigned)(acc[j] >> 32);
            g_ht[(size_t)(row0 + r    )*Oq + cg] = __uint_as_float(lo) + bt;
            g_ht[(size_t)(row0 + r + 1)*Oq + cg] = __uint_as_float(hi) + bt;
        }
        __syncthreads();
        if (tid == 0) { __threadfence(); atomicAdd(&g_cntA[b], 1); }
        return;
    }

    // ---- type B: 32 rows x 16 C cols; thread = (col e, pair p) ----
    {
        int e = tid & 15;
        int p = tid >> 4;          // 0..15 pairs -> rows 2p, 2p+1
        unsigned long long acc = 0ull;
        for (int c = 0; c < 5; c++) {
            if (c < 4) { STAGE_CHUNK((c+1)&1, c+1) }
            if (c < 4) asm volatile("cp.async.wait_group 1;" ::: "memory");
            else       asm volatile("cp.async.wait_group 0;" ::: "memory");
            __syncthreads();
            const float* wp = sW + (c & 1)*CBUF + e*CST;
            #pragma unroll 5
            for (int k4 = 0; k4 < 15; k4++) {
                float4 wv = *(const float4*)&wp[k4*4];
                const unsigned long long* hp =
                    &sh2u[(size_t)p*300 + c*KT + k4*4];
                ulonglong2 t0 = *(const ulonglong2*)(hp);
                ulonglong2 t1 = *(const ulonglong2*)(hp + 2);
                unsigned long long hk[4] = {t0.x, t0.y, t1.x, t1.y};
                #pragma unroll
                for (int kk = 0; kk < 4; kk++) {
                    unsigned long long wpk;
                    unsigned wu = __float_as_uint(((const float*)&wv)[kk]);
                    asm("mov.b64 %0, {%1, %1};" : "=l"(wpk) : "r"(wu));
                    asm("fma.rn.f32x2 %0, %1, %2, %0;"
                        : "+l"(acc) : "l"(hk[kk]), "l"(wpk));
                }
            }
            __syncthreads();
        }

        // epilogue smem (sh2/sW regions dead; se persists at tail)
        float* sy  = sm;            // 32*16
        float* sdt = sm + 1024;     // 45*16
        float* ssv = sm + 2048;     // 32*48

        {
            unsigned lo = (unsigned)(acc & 0xffffffffu);
            unsigned hi = (unsigned)(acc >> 32);
            sy[(p*2    )*16 + e] = __uint_as_float(lo);
            sy[(p*2 + 1)*16 + e] = __uint_as_float(hi);
        }
        for (int i = tid; i < Tq*Eq; i += 256) sdt[i] = dep_table[i];
        __syncthreads();

        // S[r][t] = y[r]·dt[t] + e[t]
        for (int i = tid; i < 32*TP; i += 256) {
            int r = i / TP, t = i - r*TP;
            float s;
            if (t < Tq) {
                s = se[t];
                const float* yr = sy + r*16;
                const float* dt = sdt + t*16;
                #pragma unroll
                for (int e2 = 0; e2 < Eq; e2++) s += yr[e2]*dt[e2];
            } else s = -1e30f;
            ssv[i] = s;
        }
        __syncthreads();
        if (tid < 32) {
            float m = -1e30f;
            #pragma unroll 8
            for (int t = 0; t < TP; t++) m = fmaxf(m, ssv[tid*TP + t]);
            smx[tid] = m;
        }
        __syncthreads();
        for (int i = tid; i < 32*TP; i += 256) {
            int r = i / TP, t = i - r*TP;
            float v = (t > 0 && t < Tq) ? __expf((ssv[i] - smx[r]) * 0.125f) : 0.f;
            g_E[(size_t)(row0 + r)*TP + t] = v;
        }
        __syncthreads();
        if (tid == 0) { __threadfence(); atomicAdd(&g_cntB[b], 1); }
    }
    #undef STAGE_CHUNK
}

// ---------------------------------------------------------------------------
// Inputs: h, dep_table, W1, b1, W2, b2, Wg, bg, bias, dep_type_matrix, aspect_mask
// ---------------------------------------------------------------------------
extern "C" void kernel_launch(void* const* d_in, const int* in_sizes, int n_in,
                              void* d_out, int out_size) {
    const float* h         = (const float*)d_in[0];
    const float* dep_table = (const float*)d_in[1];
    const float* W1        = (const float*)d_in[2];
    const float* b1        = (const float*)d_in[3];
    const float* W2        = (const float*)d_in[4];
    const float* b2        = (const float*)d_in[5];
    const float* Wg        = (const float*)d_in[6];
    const float* bg        = (const float*)d_in[7];
    const float* bias      = (const float*)d_in[8];
    const int*   dep       = (const int*)d_in[9];
    const unsigned char* mask = (const unsigned char*)d_in[10];

    const int smem = SMEM_FLOATS * (int)sizeof(float);   // 54016 B
    cudaFuncSetAttribute(fused_kernel,
                         cudaFuncAttributeMaxDynamicSharedMemorySize, smem);

    fused_kernel<<<704, 256, smem>>>(h, W1, b1, W2, b2, Wg, bg,
                                     dep_table, mask, dep, bias, (float*)d_out);
}

// round 15
// speedup vs baseline: 1.1622x; 1.0133x over previous
#include <cuda_runtime.h>

#define Bq 16
#define Sq 128
#define Dq 300
#define Oq 64
#define Eq 16
#define Tq 45
#define TP 48               // padded type count
#define ROWS_TOT 2048
#define WROW 316
#define KT 60               // K-chunk
#define CST 68              // smem col stride (floats): 272B, 16B-aligned
#define WBUF (64*CST)       // type-A per-buffer stride (64 cols)
#define CBUF (16*CST)       // type-B per-buffer stride (16 cols)
#define SMEM_FLOATS (4800 + 2*WBUF)   // 13504 floats = 54016 B

// __device__ scratch (allocation-free rule; zero-initialized)
__device__ float g_ht[ROWS_TOT*Oq];
__device__ float g_E [ROWS_TOT*TP];
__device__ float g_C [Eq*304];      // C[e][k], rowlen 304 (cols 300..303 unused)
__device__ int   g_syncC;           // B-block C-slice completion counter (target 64)
__device__ int   g_cntA[Bq];        // per-batch A-block done counters (target 8)
__device__ int   g_cntB[Bq];        // per-batch B-block done counters (target 4)
__device__ int   g_done;            // attn completion counter (target 256)

// ---------------------------------------------------------------------------
// cp.async helper
// ---------------------------------------------------------------------------
__device__ __forceinline__ void cp16(float* sdst, const float* gsrc) {
    unsigned a = (unsigned)__cvta_generic_to_shared(sdst);
    asm volatile("cp.async.cg.shared.global [%0], [%1], 16;" :: "r"(a), "l"(gsrc));
}

// ---------------------------------------------------------------------------
// Fused kernel: 448 blocks x 256 threads, 54 KB dynamic smem — ONE WAVE
// (148 SMs x 4 blocks = 592 slots >= 448, all blocks co-resident).
//   bx <  128 : type A gemm — 16 rows x 64 Wg cols -> g_ht; bump cntA[b].
//   128..191  : type B gemm — C-slice producer + 32 rows x 16 C cols -> y;
//               softmax table -> g_E; bump cntB[b].
//   bx >= 192 : attn (256 blocks, 8 rows x full 64 cols) — prefetch dep/bias,
//               spin on cntA/cntB[b], gather+row-sum+matmul -> out.
//               256th finisher resets all flags for the next graph replay.
// ---------------------------------------------------------------------------
__global__ void __launch_bounds__(256) fused_kernel(
        const float* __restrict__ h,
        const float* __restrict__ W1, const float* __restrict__ b1,
        const float* __restrict__ W2, const float* __restrict__ b2,
        const float* __restrict__ Wg, const float* __restrict__ bg,
        const float* __restrict__ dep_table,
        const unsigned char* __restrict__ mask8,
        const int* __restrict__ dep,
        const float* __restrict__ bias,
        float* __restrict__ out) {
    extern __shared__ float sm[];
    __shared__ int sp[5];
    __shared__ float swt[32];
    __shared__ float smx[32];

    int tid  = threadIdx.x;
    int bx   = blockIdx.x;

    // ===================== ATTN ROLE (bx >= 192) =========================
    if (bx >= 192) {
        float* sE   = sm;            // 384
        float* sht  = sm + 384;      // 8192 (128 rows x 64)
        float* sA   = sm + 8576;     // 1024
        float* sden = sm + 9600;     // 8

        int abx = bx - 192;          // 0..255
        int gr0 = abx * 8;
        int b   = gr0 >> 7;
        int g = tid >> 5, lane = tid & 31;

        // prefetch (independent of producers)
        int4 d = *(const int4*)&dep[(size_t)(gr0 + g)*Sq + lane*4];
        float bo0 = bias[lane], bo1 = bias[lane + 32];

        // wait for this batch's g_ht (8 A-blocks) and g_E (4 B-blocks)
        if (tid == 0) {
            while (atomicAdd(&g_cntA[b], 0) < 8 ||
                   atomicAdd(&g_cntB[b], 0) < 4)
                __nanosleep(128);
            __threadfence();
        }
        __syncthreads();

        // stage full h_trans batch slab (128 x 64 = 32 KB) via cp.async
        {
            const float* src = g_ht + ((size_t)b * Sq) * Oq;
            for (int i = tid; i < Sq*Oq/4; i += 256)
                cp16(&sht[i*4], src + i*4);
            asm volatile("cp.async.commit_group;" ::: "memory");
        }
        for (int i = tid; i < 8*TP; i += 256) sE[i] = g_E[(size_t)gr0*TP + i];
        __syncthreads();

        // gather e = E[ty] fused with row-sum (one warp per row)
        {
            const float* Eg = sE + g*TP;
            float e0 = Eg[d.x], e1 = Eg[d.y], e2 = Eg[d.z], e3 = Eg[d.w];
            *(float4*)&sA[g*Sq + lane*4] = make_float4(e0, e1, e2, e3);
            float s = e0 + e1 + e2 + e3;
            #pragma unroll
            for (int off = 16; off; off >>= 1)
                s += __shfl_xor_sync(0xffffffffu, s, off);
            if (lane == 0) sden[g] = 1.0f / (s + 1e-6f);
        }
        asm volatile("cp.async.wait_group 0;" ::: "memory");
        __syncthreads();

        // matmul: one warp per row; lane covers o = lane and lane+32
        const float* Ar = sA + g*Sq;
        float a0 = 0.f, a1 = 0.f;
        #pragma unroll 8
        for (int u4 = 0; u4 < 32; u4++) {
            float4 av = *(const float4*)&Ar[u4*4];
            const float* hb = sht + (u4*4)*Oq + lane;
            a0 += av.x*hb[0*Oq]      + av.y*hb[1*Oq]      + av.z*hb[2*Oq]      + av.w*hb[3*Oq];
            a1 += av.x*hb[0*Oq + 32] + av.y*hb[1*Oq + 32] + av.z*hb[2*Oq + 32] + av.w*hb[3*Oq + 32];
        }
        float den = sden[g];
        out[(size_t)(gr0 + g)*Oq + lane]      = fmaxf(a0*den + bo0, 0.f);
        out[(size_t)(gr0 + g)*Oq + lane + 32] = fmaxf(a1*den + bo1, 0.f);

        // completion count; 256th block resets all flags for next replay
        if (tid == 0) {
            int vdone = atomicAdd(&g_done, 1);
            if (vdone == 255) {
                g_done = 0;
                g_syncC = 0;
                #pragma unroll
                for (int i = 0; i < Bq; i++) { g_cntA[i] = 0; g_cntB[i] = 0; }
            }
        }
        return;
    }

    // ===================== GEMM ROLES (bx < 192) =========================
    bool tb  = bx >= 128;
    int nrows = tb ? 32 : 16;
    int row0 = tb ? (bx - 128) * 32 : bx * 16;
    int b    = row0 >> 7;
    int ncols = tb ? Eq : Oq;

    float* sh2 = sm;
    float* sW  = sm + (tb ? 9600 : 4800);
    float* se  = sm + SMEM_FLOATS - 64;   // persistent e[t] (B only)

    // ---- type-B prologue: produce C slice + Q/cb/e ----
    if (tb) {
        float* sWt1 = sm;            // tails [o][e] 1024
        float* sWt2 = sm + 1024;
        float* sW1c = sm + 2048;     // k-panel [o][j] 64*8
        float* sW2c = sm + 2560;
        float* sb1  = sm + 3072;     // 64
        float* sb2  = sm + 3136;
        float* sQ   = sm + 3200;     // 256
        float* scb  = sm + 3456;     // 16

        int bb = bx - 128;           // 0..63; slices 0..59 cover k=0..299
        int k0 = bb * 5;
        {
            int o = tid >> 2, q = tid & 3;
            *(float4*)&sWt1[o*Eq + q*4] = *(const float4*)&W1[o*WROW + Dq + q*4];
            *(float4*)&sWt2[o*Eq + q*4] = *(const float4*)&W2[o*WROW + Dq + q*4];
        }
        if (tid < 64) { sb1[tid] = b1[tid]; sb2[tid] = b2[tid]; }
        if (bb < 60 && tid < 64) {
            #pragma unroll
            for (int j = 0; j < 5; j++) {
                sW1c[tid*8 + j] = W1[tid*WROW + k0 + j];
                sW2c[tid*8 + j] = W2[tid*WROW + k0 + j];
            }
        }
        __syncthreads();

        if (bb < 60 && tid < 80) {
            int e = tid & 15, j = tid >> 4;
            float acc = 0.f;
            #pragma unroll 8
            for (int o = 0; o < Oq; o++)
                acc += sW1c[o*8 + j] * sWt2[o*Eq + e]
                     + sW2c[o*8 + j] * sWt1[o*Eq + e];
            g_C[e*304 + k0 + j] = acc;
        }
        {
            int e = tid & 15, ep = tid >> 4;
            float q = 0.f;
            #pragma unroll 8
            for (int o = 0; o < Oq; o++)
                q += sWt1[o*Eq + e] * sWt2[o*Eq + ep];
            sQ[e*16 + ep] = q;
        }
        if (tid < 16) {
            float c = 0.f;
            #pragma unroll 8
            for (int o = 0; o < Oq; o++)
                c += sb1[o] * sWt2[o*Eq + tid] + sb2[o] * sWt1[o*Eq + tid];
            scb[tid] = c;
        }
        __threadfence();
        __syncthreads();
        if (tid == 0) atomicAdd(&g_syncC, 1);

        if (tid < TP) {
            float ev = 0.f;
            if (tid < Tq) {
                float dte[Eq];
                #pragma unroll
                for (int e2 = 0; e2 < Eq; e2++) dte[e2] = dep_table[tid*Eq + e2];
                #pragma unroll
                for (int e2 = 0; e2 < Eq; e2++) {
                    float row = scb[e2];
                    #pragma unroll
                    for (int e3 = 0; e3 < Eq; e3++)
                        row += sQ[e2*16 + e3] * dte[e3];
                    ev += dte[e2] * row;
                }
            }
            se[tid] = ev;
        }
        __syncthreads();
    }

    // ---- span scan (dual bool-dtype robust) ----
    if (tid < 5) sp[tid] = (tid==0 || tid==3) ? Sq : ((tid==1 || tid==4) ? -1 : 0);
    __syncthreads();
    if (tid < 128 && mask8[(b<<7) + tid]) {
        atomicMin(&sp[0], tid); atomicMax(&sp[1], tid); atomicAdd(&sp[2], 1);
    }
    __syncthreads();
    bool valid8 = (sp[2] == 3 && sp[1] - sp[0] == 2);
    if (!valid8) {
        const int* m32 = (const int*)mask8;
        if (tid < 128 && m32[(b<<7) + tid] != 0) {
            atomicMin(&sp[3], tid); atomicMax(&sp[4], tid);
        }
    }
    __syncthreads();
    int st = valid8 ? sp[0] : sp[3];
    int en = valid8 ? sp[1] : sp[4];
    if (tid < nrows) {
        int s = (row0 + tid) & 127;
        float w;
        if (s < st)      w = 1.0f - (float)(st - s) * (1.0f/128.0f);
        else if (s > en) w = 1.0f - (float)(s - en) * (1.0f/128.0f);
        else             w = 0.0f;
        swt[tid] = w;
    }
    __syncthreads();

    // ---- stage position-weighted h, packed row pairs ----
    {
        const float4* h4 = (const float4*)(h + (size_t)row0 * Dq);
        for (int i = tid; i < nrows*75; i += 256) {
            int r = i / 75, q = i - r*75;
            float4 v = h4[i];
            float w = swt[r];
            float* dst = sh2 + ((r >> 1)*300 + q*4)*2 + (r & 1);
            dst[0] = v.x*w; dst[2] = v.y*w; dst[4] = v.z*w; dst[6] = v.w*w;
        }
    }

    // B blocks: wait for all C slices before reading g_C
    if (tb) {
        __syncthreads();
        if (tid == 0) {
            while (atomicAdd(&g_syncC, 0) < 64) __nanosleep(64);
            __threadfence();
        }
        __syncthreads();
    }

    int bufstride = tb ? CBUF : WBUF;
    #define STAGE_CHUNK(buf, cc)                                            \
        for (int i = tid; i < ncols*15; i += 256) {                         \
            int col = i / 15, q = i - col*15;                               \
            const float* src = tb                                           \
                ? g_C + (size_t)col * 304 + (cc)*KT + q*4                   \
                : Wg  + (size_t)col * Dq  + (cc)*KT + q*4;                  \
            cp16(&sW[(buf)*bufstride + col*CST + q*4], src);                \
        }                                                                   \
        asm volatile("cp.async.commit_group;" ::: "memory");

    STAGE_CHUNK(0, 0)
    const unsigned long long* sh2u = (const unsigned long long*)sh2;

    if (!tb) {
        // ---- type A: 16 rows x 64 cols; thread = (col, 2 pairs) ----
        int cg = tid & 63;
        int ph = tid >> 6;
        unsigned long long acc[2] = {0ull, 0ull};
        for (int c = 0; c < 5; c++) {
            if (c < 4) { STAGE_CHUNK((c+1)&1, c+1) }
            if (c < 4) asm volatile("cp.async.wait_group 1;" ::: "memory");
            else       asm volatile("cp.async.wait_group 0;" ::: "memory");
            __syncthreads();
            const float* wp = sW + (c & 1)*WBUF + cg*CST;
            #pragma unroll 5
            for (int k4 = 0; k4 < 15; k4++) {
                float4 wv = *(const float4*)&wp[k4*4];
                unsigned long long hk[2][4];
                #pragma unroll
                for (int j = 0; j < 2; j++) {
                    const unsigned long long* hp =
                        &sh2u[(size_t)(ph*2 + j)*300 + c*KT + k4*4];
                    ulonglong2 t0 = *(const ulonglong2*)(hp);
                    ulonglong2 t1 = *(const ulonglong2*)(hp + 2);
                    hk[j][0] = t0.x; hk[j][1] = t0.y; hk[j][2] = t1.x; hk[j][3] = t1.y;
                }
                #pragma unroll
                for (int kk = 0; kk < 4; kk++) {
                    unsigned long long wpk;
                    unsigned wu = __float_as_uint(((const float*)&wv)[kk]);
                    asm("mov.b64 %0, {%1, %1};" : "=l"(wpk) : "r"(wu));
                    #pragma unroll
                    for (int j = 0; j < 2; j++)
                        asm("fma.rn.f32x2 %0, %1, %2, %0;"
                            : "+l"(acc[j]) : "l"(hk[j][kk]), "l"(wpk));
                }
            }
            __syncthreads();
        }
        float bt = bg[cg];
        #pragma unroll
        for (int j = 0; j < 2; j++) {
            int r = (ph*2 + j)*2;
            unsigned lo = (unsigned)(acc[j] & 0xffffffffu);
            unsigned hi = (unsigned)(acc[j] >> 32);
            g_ht[(size_t)(row0 + r    )*Oq + cg] = __uint_as_float(lo) + bt;
            g_ht[(size_t)(row0 + r + 1)*Oq + cg] = __uint_as_float(hi) + bt;
        }
        __syncthreads();
        if (tid == 0) { __threadfence(); atomicAdd(&g_cntA[b], 1); }
        return;
    }

    // ---- type B: 32 rows x 16 C cols; thread = (col e, pair p) ----
    {
        int e = tid & 15;
        int p = tid >> 4;          // 0..15 pairs -> rows 2p, 2p+1
        unsigned long long acc = 0ull;
        for (int c = 0; c < 5; c++) {
            if (c < 4) { STAGE_CHUNK((c+1)&1, c+1) }
            if (c < 4) asm volatile("cp.async.wait_group 1;" ::: "memory");
            else       asm volatile("cp.async.wait_group 0;" ::: "memory");
            __syncthreads();
            const float* wp = sW + (c & 1)*CBUF + e*CST;
            #pragma unroll 5
            for (int k4 = 0; k4 < 15; k4++) {
                float4 wv = *(const float4*)&wp[k4*4];
                const unsigned long long* hp =
                    &sh2u[(size_t)p*300 + c*KT + k4*4];
                ulonglong2 t0 = *(const ulonglong2*)(hp);
                ulonglong2 t1 = *(const ulonglong2*)(hp + 2);
                unsigned long long hk[4] = {t0.x, t0.y, t1.x, t1.y};
                #pragma unroll
                for (int kk = 0; kk < 4; kk++) {
                    unsigned long long wpk;
                    unsigned wu = __float_as_uint(((const float*)&wv)[kk]);
                    asm("mov.b64 %0, {%1, %1};" : "=l"(wpk) : "r"(wu));
                    asm("fma.rn.f32x2 %0, %1, %2, %0;"
                        : "+l"(acc) : "l"(hk[kk]), "l"(wpk));
                }
            }
            __syncthreads();
        }

        // epilogue smem (sh2/sW regions dead; se persists at tail)
        float* sy  = sm;            // 32*16
        float* sdt = sm + 1024;     // 45*16
        float* ssv = sm + 2048;     // 32*48

        {
            unsigned lo = (unsigned)(acc & 0xffffffffu);
            unsigned hi = (unsigned)(acc >> 32);
            sy[(p*2    )*16 + e] = __uint_as_float(lo);
            sy[(p*2 + 1)*16 + e] = __uint_as_float(hi);
        }
        for (int i = tid; i < Tq*Eq; i += 256) sdt[i] = dep_table[i];
        __syncthreads();

        // S[r][t] = y[r]·dt[t] + e[t]
        for (int i = tid; i < 32*TP; i += 256) {
            int r = i / TP, t = i - r*TP;
            float s;
            if (t < Tq) {
                s = se[t];
                const float* yr = sy + r*16;
                const float* dt = sdt + t*16;
                #pragma unroll
                for (int e2 = 0; e2 < Eq; e2++) s += yr[e2]*dt[e2];
            } else s = -1e30f;
            ssv[i] = s;
        }
        __syncthreads();
        if (tid < 32) {
            float m = -1e30f;
            #pragma unroll 8
            for (int t = 0; t < TP; t++) m = fmaxf(m, ssv[tid*TP + t]);
            smx[tid] = m;
        }
        __syncthreads();
        for (int i = tid; i < 32*TP; i += 256) {
            int r = i / TP, t = i - r*TP;
            float v = (t > 0 && t < Tq) ? __expf((ssv[i] - smx[r]) * 0.125f) : 0.f;
            g_E[(size_t)(row0 + r)*TP + t] = v;
        }
        __syncthreads();
        if (tid == 0) { __threadfence(); atomicAdd(&g_cntB[b], 1); }
    }
    #undef STAGE_CHUNK
}

// ---------------------------------------------------------------------------
// Inputs: h, dep_table, W1, b1, W2, b2, Wg, bg, bias, dep_type_matrix, aspect_mask
// ---------------------------------------------------------------------------
extern "C" void kernel_launch(void* const* d_in, const int* in_sizes, int n_in,
                              void* d_out, int out_size) {
    const float* h         = (const float*)d_in[0];
    const float* dep_table = (const float*)d_in[1];
    const float* W1        = (const float*)d_in[2];
    const float* b1        = (const float*)d_in[3];
    const float* W2        = (const float*)d_in[4];
    const float* b2        = (const float*)d_in[5];
    const float* Wg        = (const float*)d_in[6];
    const float* bg        = (const float*)d_in[7];
    const float* bias      = (const float*)d_in[8];
    const int*   dep       = (const int*)d_in[9];
    const unsigned char* mask = (const unsigned char*)d_in[10];

    const int smem = SMEM_FLOATS * (int)sizeof(float);   // 54016 B
    cudaFuncSetAttribute(fused_kernel,
                         cudaFuncAttributeMaxDynamicSharedMemorySize, smem);

    fused_kernel<<<448, 256, smem>>>(h, W1, b1, W2, b2, Wg, bg,
                                     dep_table, mask, dep, bias, (float*)d_out);
}